// round 2
// baseline (speedup 1.0000x reference)
#include <cuda_runtime.h>
#include <math.h>

// ---------------------------------------------------------------------------
// localAE: two stacked GCNConv layers.
//   loc_emb = GCN(x, W_enc, b_enc)          [N, 64]
//   loc_rec = GCN(loc_emb, W_dec, b_dec)    [N, 128]
// GCN(x) = D^-1/2 (A+I) D^-1/2 (x W) + b, deg = in-degree(dst) + 1
// Edge index arrives as int32 (harness converts int64 -> int32).
// ---------------------------------------------------------------------------

#define NN 100000
#define MAXC 128

// scratch (static device globals: allocation-free)
__device__ float g_h[(size_t)NN * MAXC];   // h = x @ W (pre-aggregation)
__device__ float g_deg[NN];
__device__ float g_dinv[NN];

// ---------------------------------------------------------------------------
__global__ void k_init_deg(int n) {
    int i = blockIdx.x * blockDim.x + threadIdx.x;
    if (i < n) g_deg[i] = 1.0f;  // self-loop
}

__global__ void k_count(const int* __restrict__ dst, int E) {
    int e = blockIdx.x * blockDim.x + threadIdx.x;
    if (e < E) atomicAdd(&g_deg[dst[e]], 1.0f);
}

__global__ void k_dinv(int n) {
    int i = blockIdx.x * blockDim.x + threadIdx.x;
    if (i < n) g_dinv[i] = 1.0f / sqrtf(g_deg[i]);  // deg >= 1 always
}

// ---------------------------------------------------------------------------
// GEMM: H[n, COUT] = X[n, CIN] @ W[CIN, COUT]
// Epilogue writes H to g_h AND writes the self-loop + bias term to OUTF:
//   OUTF[i,c] = H[i,c] * dinv[i]^2 + b[c]
// (WRITES the whole output region every call -> graph-replay safe;
//  the edge kernel then atomically accumulates on top.)
// Block tile: 64 nodes x COUT channels. Thread tile: 8 nodes x 4 channels.
// ---------------------------------------------------------------------------
template<int CIN, int COUT>
__global__ void k_gemm(const float* __restrict__ X, const float* __restrict__ W,
                       const float* __restrict__ B, float* __restrict__ OUTF, int n) {
    constexpr int BM = 64, TM = 8, TN = 4, KC = 32;
    constexpr int CG = COUT / TN;       // channel groups
    constexpr int NG = BM / TM;         // node groups
    constexpr int NT = CG * NG;         // threads per block
    constexpr int XP = CIN + 4;         // padded x row
    __shared__ float xs[BM * XP];
    __shared__ float ws[KC * COUT];

    const int t  = threadIdx.x;
    const int n0 = blockIdx.x * BM;

    // stage X tile (tile rows are contiguous in global)
    for (int i = t * 4; i < BM * CIN; i += NT * 4) {
        int r = i / CIN, col = i % CIN;
        int node = n0 + r;
        float4 v = make_float4(0.f, 0.f, 0.f, 0.f);
        if (node < n) v = *(const float4*)(X + (size_t)node * CIN + col);
        *(float4*)(xs + r * XP + col) = v;
    }

    const int cg = t % CG;
    const int ng = t / CG;
    float4 acc[TM];
#pragma unroll
    for (int i = 0; i < TM; i++) acc[i] = make_float4(0.f, 0.f, 0.f, 0.f);

    for (int kc = 0; kc < CIN; kc += KC) {
        __syncthreads();  // xs done (first iter) / previous ws reads done
        for (int i = t * 4; i < KC * COUT; i += NT * 4)
            *(float4*)(ws + i) = *(const float4*)(W + kc * COUT + i);
        __syncthreads();

#pragma unroll
        for (int k0 = 0; k0 < KC; k0 += 4) {
            float4 w0 = *(float4*)(ws + (k0 + 0) * COUT + cg * 4);
            float4 w1 = *(float4*)(ws + (k0 + 1) * COUT + cg * 4);
            float4 w2 = *(float4*)(ws + (k0 + 2) * COUT + cg * 4);
            float4 w3 = *(float4*)(ws + (k0 + 3) * COUT + cg * 4);
#pragma unroll
            for (int i = 0; i < TM; i++) {
                float4 xv = *(float4*)(xs + (ng * TM + i) * XP + kc + k0);
                acc[i].x += xv.x * w0.x + xv.y * w1.x + xv.z * w2.x + xv.w * w3.x;
                acc[i].y += xv.x * w0.y + xv.y * w1.y + xv.z * w2.y + xv.w * w3.y;
                acc[i].z += xv.x * w0.z + xv.y * w1.z + xv.z * w2.z + xv.w * w3.z;
                acc[i].w += xv.x * w0.w + xv.y * w1.w + xv.z * w2.w + xv.w * w3.w;
            }
        }
    }

    float4 bv = *(const float4*)(B + cg * 4);
#pragma unroll
    for (int i = 0; i < TM; i++) {
        int node = n0 + ng * TM + i;
        if (node < n) {
            *(float4*)(g_h + (size_t)node * COUT + cg * 4) = acc[i];
            float di = g_dinv[node];
            float sc = di * di;  // self-loop norm = dinv^2 (exactly 1/deg)
            float4 o = make_float4(acc[i].x * sc + bv.x, acc[i].y * sc + bv.y,
                                   acc[i].z * sc + bv.z, acc[i].w * sc + bv.w);
            *(float4*)(OUTF + (size_t)node * COUT + cg * 4) = o;
        }
    }
}

// ---------------------------------------------------------------------------
// Edge scatter: out[dst] += h[src] * dinv[src] * dinv[dst]
// One thread per (edge, 4-channel chunk); vectorized red.global.add.v4.f32.
// ---------------------------------------------------------------------------
template<int COUT>
__global__ void k_edge(const int* __restrict__ src,
                       const int* __restrict__ dst,
                       float* __restrict__ out, int E) {
    constexpr int CH = COUT / 4;
    int tid = blockIdx.x * blockDim.x + threadIdx.x;
    int e = tid / CH;
    int c = (tid % CH) * 4;
    if (e >= E) return;
    int s = src[e];
    int d = dst[e];
    float nm = g_dinv[s] * g_dinv[d];
    float4 m = *(const float4*)(g_h + (size_t)s * COUT + c);
    float* p = out + (size_t)d * COUT + c;
    asm volatile("red.global.add.v4.f32 [%0], {%1, %2, %3, %4};"
                 :: "l"(p), "f"(m.x * nm), "f"(m.y * nm),
                    "f"(m.z * nm), "f"(m.w * nm)
                 : "memory");
}

// ---------------------------------------------------------------------------
extern "C" void kernel_launch(void* const* d_in, const int* in_sizes, int n_in,
                              void* d_out, int out_size) {
    const float* x     = (const float*)d_in[0];
    const int*   ei    = (const int*)d_in[1];
    const float* W_enc = (const float*)d_in[2];
    const float* b_enc = (const float*)d_in[3];
    const float* W_dec = (const float*)d_in[4];
    const float* b_dec = (const float*)d_in[5];

    const int N = in_sizes[0] / 128;   // 100000
    const int E = in_sizes[1] / 2;     // 1600000
    const int* src = ei;
    const int* dst = ei + E;

    float* out_emb = (float*)d_out;                     // [N, 64]
    float* out_rec = out_emb + (size_t)N * 64;          // [N, 128]

    const int TB = 256;

    // degree + normalization
    k_init_deg<<<(N + TB - 1) / TB, TB>>>(N);
    k_count<<<(E + TB - 1) / TB, TB>>>(dst, E);
    k_dinv<<<(N + TB - 1) / TB, TB>>>(N);

    // layer 1: enc (CIN=128, COUT=64) -> 128 threads/block
    k_gemm<128, 64><<<(N + 63) / 64, 128>>>(x, W_enc, b_enc, out_emb, N);
    {
        long long tot = (long long)E * (64 / 4);
        k_edge<64><<<(int)((tot + TB - 1) / TB), TB>>>(src, dst, out_emb, E);
    }

    // layer 2: dec (CIN=64, COUT=128) -> 256 threads/block
    k_gemm<64, 128><<<(N + 63) / 64, 256>>>(out_emb, W_dec, b_dec, out_rec, N);
    {
        long long tot = (long long)E * (128 / 4);
        k_edge<128><<<(int)((tot + TB - 1) / TB), TB>>>(src, dst, out_rec, E);
    }
}

// round 4
// speedup vs baseline: 1.3667x; 1.3667x over previous
#include <cuda_runtime.h>
#include <math.h>

// ---------------------------------------------------------------------------
// localAE: two stacked GCNConv layers.
//   loc_emb = GCN(x, W_enc, b_enc)          [N, 64]
//   loc_rec = GCN(loc_emb, W_dec, b_dec)    [N, 128]
// GCN(x) = D^-1/2 (A+I) D^-1/2 (x W) + b, deg = in-degree(dst) + 1
//
// Decoder uses linearity of aggregation:  agg(y) @ W == agg(y @ W)
// so we aggregate loc_emb at 64 channels FIRST, then GEMM to 128 channels.
//
// NOTE: __device__ globals must NOT be passed to kernels by name from host
// code (host shadow symbol != device address; on GB300/ATS it silently reads
// host memory). We resolve the device address via cudaGetSymbolAddress.
// ---------------------------------------------------------------------------

#define NN 100000
#define MAXC 128

// scratch (static device globals: allocation-free)
__device__ float g_h[(size_t)NN * MAXC];   // layer1: H1 = x@W_enc; layer2: agg buffer
__device__ float g_deg[NN];
__device__ float g_dinv[NN];

// ---------------------------------------------------------------------------
__global__ void k_init_deg(int n) {
    int i = blockIdx.x * blockDim.x + threadIdx.x;
    if (i < n) g_deg[i] = 1.0f;  // self-loop
}

__global__ void k_count(const int* __restrict__ dst, int E) {
    int e = blockIdx.x * blockDim.x + threadIdx.x;
    if (e < E) atomicAdd(&g_deg[dst[e]], 1.0f);
}

__global__ void k_dinv(int n) {
    int i = blockIdx.x * blockDim.x + threadIdx.x;
    if (i < n) g_dinv[i] = 1.0f / sqrtf(g_deg[i]);  // deg >= 1 always
}

// ---------------------------------------------------------------------------
// GEMM: acc[n, COUT] = X[n, CIN] @ W[CIN, COUT]
// AGG_EPI=true : write acc to HOUT AND OUTF = acc*dinv^2 + b   (encoder)
// AGG_EPI=false: write OUTF = acc + b only                     (decoder, pure)
// Block tile: 64 nodes x COUT channels. Thread tile: 8 nodes x 4 channels.
// ---------------------------------------------------------------------------
template<int CIN, int COUT, bool AGG_EPI>
__global__ void k_gemm(const float* __restrict__ X, const float* __restrict__ W,
                       const float* __restrict__ B, float* __restrict__ HOUT,
                       float* __restrict__ OUTF, int n) {
    constexpr int BM = 64, TM = 8, TN = 4, KC = 32;
    constexpr int CG = COUT / TN;       // channel groups
    constexpr int NG = BM / TM;         // node groups
    constexpr int NT = CG * NG;         // threads per block
    constexpr int XP = CIN + 4;         // padded x row
    __shared__ float xs[BM * XP];
    __shared__ float ws[KC * COUT];

    const int t  = threadIdx.x;
    const int n0 = blockIdx.x * BM;

    // stage X tile (tile rows are contiguous in global)
    for (int i = t * 4; i < BM * CIN; i += NT * 4) {
        int r = i / CIN, col = i % CIN;
        int node = n0 + r;
        float4 v = make_float4(0.f, 0.f, 0.f, 0.f);
        if (node < n) v = *(const float4*)(X + (size_t)node * CIN + col);
        *(float4*)(xs + r * XP + col) = v;
    }

    const int cg = t % CG;
    const int ng = t / CG;
    float4 acc[TM];
#pragma unroll
    for (int i = 0; i < TM; i++) acc[i] = make_float4(0.f, 0.f, 0.f, 0.f);

    for (int kc = 0; kc < CIN; kc += KC) {
        __syncthreads();  // xs done (first iter) / previous ws reads done
        for (int i = t * 4; i < KC * COUT; i += NT * 4)
            *(float4*)(ws + i) = *(const float4*)(W + kc * COUT + i);
        __syncthreads();

#pragma unroll
        for (int k0 = 0; k0 < KC; k0 += 4) {
            float4 w0 = *(float4*)(ws + (k0 + 0) * COUT + cg * 4);
            float4 w1 = *(float4*)(ws + (k0 + 1) * COUT + cg * 4);
            float4 w2 = *(float4*)(ws + (k0 + 2) * COUT + cg * 4);
            float4 w3 = *(float4*)(ws + (k0 + 3) * COUT + cg * 4);
#pragma unroll
            for (int i = 0; i < TM; i++) {
                float4 xv = *(float4*)(xs + (ng * TM + i) * XP + kc + k0);
                acc[i].x += xv.x * w0.x + xv.y * w1.x + xv.z * w2.x + xv.w * w3.x;
                acc[i].y += xv.x * w0.y + xv.y * w1.y + xv.z * w2.y + xv.w * w3.y;
                acc[i].z += xv.x * w0.z + xv.y * w1.z + xv.z * w2.z + xv.w * w3.z;
                acc[i].w += xv.x * w0.w + xv.y * w1.w + xv.z * w2.w + xv.w * w3.w;
            }
        }
    }

    float4 bv = *(const float4*)(B + cg * 4);
#pragma unroll
    for (int i = 0; i < TM; i++) {
        int node = n0 + ng * TM + i;
        if (node < n) {
            if (AGG_EPI) {
                *(float4*)(HOUT + (size_t)node * COUT + cg * 4) = acc[i];
                float di = g_dinv[node];
                float sc = di * di;  // self-loop norm = dinv^2 (exactly 1/deg)
                float4 o = make_float4(acc[i].x * sc + bv.x, acc[i].y * sc + bv.y,
                                       acc[i].z * sc + bv.z, acc[i].w * sc + bv.w);
                *(float4*)(OUTF + (size_t)node * COUT + cg * 4) = o;
            } else {
                float4 o = make_float4(acc[i].x + bv.x, acc[i].y + bv.y,
                                       acc[i].z + bv.z, acc[i].w + bv.w);
                *(float4*)(OUTF + (size_t)node * COUT + cg * 4) = o;
            }
        }
    }
}

// ---------------------------------------------------------------------------
// Edge scatter: out[dst] += feat[src] * dinv[src] * dinv[dst]
// One thread per (edge, 4-channel chunk); vectorized red.global.add.v4.f32.
// ---------------------------------------------------------------------------
template<int C>
__global__ void k_edge(const int* __restrict__ src,
                       const int* __restrict__ dst,
                       const float* __restrict__ feat,
                       float* __restrict__ out, int E) {
    constexpr int CH = C / 4;
    int tid = blockIdx.x * blockDim.x + threadIdx.x;
    int e = tid / CH;
    int c = (tid % CH) * 4;
    if (e >= E) return;
    int s = src[e];
    int d = dst[e];
    float nm = g_dinv[s] * g_dinv[d];
    float4 m = *(const float4*)(feat + (size_t)s * C + c);
    float* p = out + (size_t)d * C + c;
    asm volatile("red.global.add.v4.f32 [%0], {%1, %2, %3, %4};"
                 :: "l"(p), "f"(m.x * nm), "f"(m.y * nm),
                    "f"(m.z * nm), "f"(m.w * nm)
                 : "memory");
}

// ---------------------------------------------------------------------------
// Self-loop init for decoder aggregation: hbuf[i] = emb[i] * dinv[i]^2
// ---------------------------------------------------------------------------
__global__ void k_selfinit(const float* __restrict__ emb,
                           float* __restrict__ hbuf, int n) {
    int tid = blockIdx.x * blockDim.x + threadIdx.x;   // one float4 per thread
    int i = tid / 16;        // node
    int c = (tid % 16) * 4;  // channel
    if (i >= n) return;
    float di = g_dinv[i];
    float sc = di * di;
    float4 v = *(const float4*)(emb + (size_t)i * 64 + c);
    v.x *= sc; v.y *= sc; v.z *= sc; v.w *= sc;
    *(float4*)(hbuf + (size_t)i * 64 + c) = v;
}

// ---------------------------------------------------------------------------
extern "C" void kernel_launch(void* const* d_in, const int* in_sizes, int n_in,
                              void* d_out, int out_size) {
    const float* x     = (const float*)d_in[0];
    const int*   ei    = (const int*)d_in[1];
    const float* W_enc = (const float*)d_in[2];
    const float* b_enc = (const float*)d_in[3];
    const float* W_dec = (const float*)d_in[4];
    const float* b_dec = (const float*)d_in[5];

    const int N = in_sizes[0] / 128;   // 100000
    const int E = in_sizes[1] / 2;     // 1600000
    const int* src = ei;
    const int* dst = ei + E;

    float* out_emb = (float*)d_out;                     // [N, 64]
    float* out_rec = out_emb + (size_t)N * 64;          // [N, 128]

    // REAL device address of the scratch symbol (host shadow addr is invalid)
    float* hbuf = nullptr;
    cudaGetSymbolAddress((void**)&hbuf, g_h);

    const int TB = 256;

    // degree + normalization
    k_init_deg<<<(N + TB - 1) / TB, TB>>>(N);
    k_count<<<(E + TB - 1) / TB, TB>>>(dst, E);
    k_dinv<<<(N + TB - 1) / TB, TB>>>(N);

    // ---- layer 1 (encoder): GEMM first (128->64), aggregate at 64 ch ----
    k_gemm<128, 64, true><<<(N + 63) / 64, 128>>>(x, W_enc, b_enc, hbuf, out_emb, N);
    {
        long long tot = (long long)E * (64 / 4);
        k_edge<64><<<(int)((tot + TB - 1) / TB), TB>>>(src, dst, hbuf, out_emb, E);
    }

    // ---- layer 2 (decoder): aggregate at 64 ch FIRST, then GEMM (64->128) ----
    {
        long long tot = (long long)N * 16;
        k_selfinit<<<(int)((tot + TB - 1) / TB), TB>>>(out_emb, hbuf, N);
    }
    {
        long long tot = (long long)E * (64 / 4);
        k_edge<64><<<(int)((tot + TB - 1) / TB), TB>>>(src, dst, out_emb, hbuf, E);
    }
    k_gemm<64, 128, false><<<(N + 63) / 64, 256>>>(hbuf, W_dec, b_dec, nullptr, out_rec, N);
}

// round 5
// speedup vs baseline: 1.8029x; 1.3191x over previous
#include <cuda_runtime.h>
#include <math.h>

// ---------------------------------------------------------------------------
// localAE: two stacked GCNConv layers.
//   loc_emb = GCN(x, W_enc, b_enc)          [N, 64]
//   loc_rec = GCN(loc_emb, W_dec, b_dec)    [N, 128]
// GCN(x) = D^-1/2 (A+I) D^-1/2 (x W) + b, deg = in-degree(dst) + 1
//
// Structure (uses linearity of aggregation for the decoder):
//   g_h   = x @ W_enc                        (gemm, 128->64)
//   emb   = dinv[d]*(sum_in h[s]*dinv[s] + h[d]*dinv[d]) + b_enc   (CSR gather)
//   g_h   = dinv[d]*(sum_in emb[s]*dinv[s] + emb[d]*dinv[d])       (CSR gather)
//   rec   = g_h @ W_dec + b_dec              (gemm, 64->128)
// CSR built per-launch from edge_index (grouped by dst) -> NO feature atomics.
// ---------------------------------------------------------------------------

#define NN   100000
#define EMAX 1600000
#define NB_SCAN ((NN + 1023) / 1024)   // 98

// scratch (static device globals: allocation-free)
__device__ float g_h[(size_t)NN * 64];  // layer1: x@W_enc ; layer2: aggregated emb
__device__ float g_dinv[NN];
__device__ int   g_cnt[NN];             // in-degree (without self loop)
__device__ int   g_ptr[NN];             // CSR row start (exclusive scan of cnt)
__device__ int   g_cur[NN];             // fill cursor
__device__ int   g_csr[EMAX];           // src node per edge, grouped by dst
__device__ int   g_bsum[NB_SCAN];       // scan block totals
__device__ int   g_boff[NB_SCAN];       // scan block offsets

// ---------------------------------------------------------------------------
__global__ void k_zero_cnt(int n) {
    int i = blockIdx.x * blockDim.x + threadIdx.x;
    if (i < n) g_cnt[i] = 0;
}

__global__ void k_hist(const int* __restrict__ dst, int E) {
    int e = blockIdx.x * blockDim.x + threadIdx.x;
    if (e < E) atomicAdd(&g_cnt[dst[e]], 1);
}

__global__ void k_dinv(int n) {
    int i = blockIdx.x * blockDim.x + threadIdx.x;
    if (i < n) g_dinv[i] = 1.0f / sqrtf((float)(g_cnt[i] + 1));  // +1 self loop
}

// ---- exclusive scan of g_cnt -> g_ptr (3 kernels) -------------------------
__global__ void k_scan1(int n) {           // block = 1024
    __shared__ int sh[1024];
    int t  = threadIdx.x;
    int gi = blockIdx.x * 1024 + t;
    int v = (gi < n) ? g_cnt[gi] : 0;
    sh[t] = v;
    __syncthreads();
#pragma unroll
    for (int off = 1; off < 1024; off <<= 1) {
        int a = (t >= off) ? sh[t - off] : 0;
        __syncthreads();
        sh[t] += a;
        __syncthreads();
    }
    if (gi < n) g_ptr[gi] = sh[t] - v;       // exclusive
    if (t == 1023) g_bsum[blockIdx.x] = sh[t];
}

__global__ void k_scan2(int nb) {           // single block, 128 threads
    __shared__ int sh[128];
    int t = threadIdx.x;
    int v = (t < nb) ? g_bsum[t] : 0;
    sh[t] = v;
    __syncthreads();
#pragma unroll
    for (int off = 1; off < 128; off <<= 1) {
        int a = (t >= off) ? sh[t - off] : 0;
        __syncthreads();
        sh[t] += a;
        __syncthreads();
    }
    if (t < nb) g_boff[t] = sh[t] - v;       // exclusive
}

__global__ void k_scan3(int n) {            // block = 1024
    int gi = blockIdx.x * 1024 + threadIdx.x;
    if (gi < n) {
        int p = g_ptr[gi] + g_boff[blockIdx.x];
        g_ptr[gi] = p;
        g_cur[gi] = p;
    }
}

__global__ void k_fill(const int* __restrict__ src, const int* __restrict__ dst,
                       int E) {
    int e = blockIdx.x * blockDim.x + threadIdx.x;
    if (e < E) {
        int pos = atomicAdd(&g_cur[dst[e]], 1);
        g_csr[pos] = src[e];
    }
}

// ---------------------------------------------------------------------------
// CSR aggregation at 64 channels. One warp per node.
//   out[d] = dinv[d] * (sum_{s in in(d)} feat[s]*dinv[s] + feat[d]*dinv[d]) (+b)
// Lanes 0-15 / 16-31 handle even / odd edges; 16 lanes cover 64 ch as float4.
// ---------------------------------------------------------------------------
template<bool BIAS>
__global__ void k_agg64(const float* __restrict__ feat,
                        float* __restrict__ out,
                        const float* __restrict__ B, int n) {
    int w    = (blockIdx.x * blockDim.x + threadIdx.x) >> 5;   // node
    int lane = threadIdx.x & 31;
    if (w >= n) return;
    int c4   = lane & 15;        // float4 channel group
    int half = lane >> 4;        // 0 or 1
    int start = g_ptr[w];
    int cnt   = g_cnt[w];

    float4 acc = make_float4(0.f, 0.f, 0.f, 0.f);
    for (int k = half; k < cnt; k += 2) {
        int s = g_csr[start + k];
        float sc = g_dinv[s];
        float4 v = *(const float4*)(feat + (size_t)s * 64 + c4 * 4);
        acc.x += v.x * sc; acc.y += v.y * sc;
        acc.z += v.z * sc; acc.w += v.w * sc;
    }
    if (half == 0) {             // self loop: s = d, scale dinv[d]
        float sc = g_dinv[w];
        float4 v = *(const float4*)(feat + (size_t)w * 64 + c4 * 4);
        acc.x += v.x * sc; acc.y += v.y * sc;
        acc.z += v.z * sc; acc.w += v.w * sc;
    }
    acc.x += __shfl_down_sync(0xffffffffu, acc.x, 16);
    acc.y += __shfl_down_sync(0xffffffffu, acc.y, 16);
    acc.z += __shfl_down_sync(0xffffffffu, acc.z, 16);
    acc.w += __shfl_down_sync(0xffffffffu, acc.w, 16);

    if (half == 0) {
        float dd = g_dinv[w];
        float4 o;
        if (BIAS) {
            float4 bv = *(const float4*)(B + c4 * 4);
            o = make_float4(acc.x * dd + bv.x, acc.y * dd + bv.y,
                            acc.z * dd + bv.z, acc.w * dd + bv.w);
        } else {
            o = make_float4(acc.x * dd, acc.y * dd, acc.z * dd, acc.w * dd);
        }
        *(float4*)(out + (size_t)w * 64 + c4 * 4) = o;
    }
}

// ---------------------------------------------------------------------------
// GEMM: OUT[n, COUT] = X[n, CIN] @ W[CIN, COUT]  (+ bias if BIAS)
// Block tile: 64 nodes x COUT channels. Thread tile: 8 nodes x 4 channels.
// ---------------------------------------------------------------------------
template<int CIN, int COUT, bool BIAS>
__global__ void k_gemm(const float* __restrict__ X, const float* __restrict__ W,
                       const float* __restrict__ B, float* __restrict__ OUT, int n) {
    constexpr int BM = 64, TM = 8, TN = 4, KC = 32;
    constexpr int CG = COUT / TN;
    constexpr int NG = BM / TM;
    constexpr int NT = CG * NG;
    constexpr int XP = CIN + 4;
    __shared__ float xs[BM * XP];
    __shared__ float ws[KC * COUT];

    const int t  = threadIdx.x;
    const int n0 = blockIdx.x * BM;

    for (int i = t * 4; i < BM * CIN; i += NT * 4) {
        int r = i / CIN, col = i % CIN;
        int node = n0 + r;
        float4 v = make_float4(0.f, 0.f, 0.f, 0.f);
        if (node < n) v = *(const float4*)(X + (size_t)node * CIN + col);
        *(float4*)(xs + r * XP + col) = v;
    }

    const int cg = t % CG;
    const int ng = t / CG;
    float4 acc[TM];
#pragma unroll
    for (int i = 0; i < TM; i++) acc[i] = make_float4(0.f, 0.f, 0.f, 0.f);

    for (int kc = 0; kc < CIN; kc += KC) {
        __syncthreads();
        for (int i = t * 4; i < KC * COUT; i += NT * 4)
            *(float4*)(ws + i) = *(const float4*)(W + kc * COUT + i);
        __syncthreads();

#pragma unroll
        for (int k0 = 0; k0 < KC; k0 += 4) {
            float4 w0 = *(float4*)(ws + (k0 + 0) * COUT + cg * 4);
            float4 w1 = *(float4*)(ws + (k0 + 1) * COUT + cg * 4);
            float4 w2 = *(float4*)(ws + (k0 + 2) * COUT + cg * 4);
            float4 w3 = *(float4*)(ws + (k0 + 3) * COUT + cg * 4);
#pragma unroll
            for (int i = 0; i < TM; i++) {
                float4 xv = *(float4*)(xs + (ng * TM + i) * XP + kc + k0);
                acc[i].x += xv.x * w0.x + xv.y * w1.x + xv.z * w2.x + xv.w * w3.x;
                acc[i].y += xv.x * w0.y + xv.y * w1.y + xv.z * w2.y + xv.w * w3.y;
                acc[i].z += xv.x * w0.z + xv.y * w1.z + xv.z * w2.z + xv.w * w3.z;
                acc[i].w += xv.x * w0.w + xv.y * w1.w + xv.z * w2.w + xv.w * w3.w;
            }
        }
    }

    float4 bv = make_float4(0.f, 0.f, 0.f, 0.f);
    if (BIAS) bv = *(const float4*)(B + cg * 4);
#pragma unroll
    for (int i = 0; i < TM; i++) {
        int node = n0 + ng * TM + i;
        if (node < n) {
            float4 o = acc[i];
            if (BIAS) { o.x += bv.x; o.y += bv.y; o.z += bv.z; o.w += bv.w; }
            *(float4*)(OUT + (size_t)node * COUT + cg * 4) = o;
        }
    }
}

// ---------------------------------------------------------------------------
extern "C" void kernel_launch(void* const* d_in, const int* in_sizes, int n_in,
                              void* d_out, int out_size) {
    const float* x     = (const float*)d_in[0];
    const int*   ei    = (const int*)d_in[1];
    const float* W_enc = (const float*)d_in[2];
    const float* b_enc = (const float*)d_in[3];
    const float* W_dec = (const float*)d_in[4];
    const float* b_dec = (const float*)d_in[5];

    const int N = in_sizes[0] / 128;   // 100000
    const int E = in_sizes[1] / 2;     // 1600000
    const int* src = ei;
    const int* dst = ei + E;

    float* out_emb = (float*)d_out;                 // [N, 64]
    float* out_rec = out_emb + (size_t)N * 64;      // [N, 128]

    // real device address of the scratch symbol (host shadow addr is invalid)
    float* hbuf = nullptr;
    cudaGetSymbolAddress((void**)&hbuf, g_h);

    const int TB = 256;
    const int nbN = (N + TB - 1) / TB;
    const int nbE = (E + TB - 1) / TB;

    // ---- degree + dinv + CSR build ----
    k_zero_cnt<<<nbN, TB>>>(N);
    k_hist<<<nbE, TB>>>(dst, E);
    k_dinv<<<nbN, TB>>>(N);
    k_scan1<<<NB_SCAN, 1024>>>(N);
    k_scan2<<<1, 128>>>(NB_SCAN);
    k_scan3<<<NB_SCAN, 1024>>>(N);
    k_fill<<<nbE, TB>>>(src, dst, E);

    // ---- layer 1 (encoder): gemm (128->64) then CSR aggregate + bias ----
    k_gemm<128, 64, false><<<(N + 63) / 64, 128>>>(x, W_enc, nullptr, hbuf, N);
    {
        int blocks = (N * 32 + TB - 1) / TB;   // warp per node
        k_agg64<true><<<blocks, TB>>>(hbuf, out_emb, b_enc, N);
    }

    // ---- layer 2 (decoder): CSR aggregate (no bias) then gemm (64->128) ----
    {
        int blocks = (N * 32 + TB - 1) / TB;
        k_agg64<false><<<blocks, TB>>>(out_emb, hbuf, nullptr, N);
    }
    k_gemm<64, 128, true><<<(N + 63) / 64, 256>>>(hbuf, W_dec, b_dec, out_rec, N);
}